// round 1
// baseline (speedup 1.0000x reference)
#include <cuda_runtime.h>
#include <cstdint>
#include <cstddef>

#define NTOK 2048    // B*L tokens
#define DM   1024
#define DI   2048
#define DS   16
#define LSEQ 1024

// ------------------------- scratch (static device memory) -------------------------
__device__ float g_xn[NTOK * DM];        // rmsnormed x
__device__ float g_proj[NTOK * 2 * DI];  // [x_branch | gate]
__device__ float g_xc[NTOK * DI];        // conv+silu output
__device__ float g_dt[NTOK * DI];        // dt after softplus+softclamp
__device__ float g_Bp[NTOK * DS];
__device__ float g_Cp[NTOK * DS];
__device__ float g_xssm[NTOK * DI];
__device__ float g_gated[NTOK * DI];

// ------------------------- rmsnorm -------------------------
__global__ void rmsnorm_kernel(const float* __restrict__ x, const float* __restrict__ w)
{
    __shared__ float red[8];
    int token = blockIdx.x;
    int tid = threadIdx.x;  // 256
    const float4* xr = reinterpret_cast<const float4*>(x + (size_t)token * DM);
    float4 v = xr[tid];
    float ss = v.x * v.x + v.y * v.y + v.z * v.z + v.w * v.w;
#pragma unroll
    for (int o = 16; o; o >>= 1) ss += __shfl_xor_sync(0xffffffffu, ss, o);
    if ((tid & 31) == 0) red[tid >> 5] = ss;
    __syncthreads();
    float tot = 0.f;
#pragma unroll
    for (int i = 0; i < 8; i++) tot += red[i];
    float r = rsqrtf(tot * (1.f / (float)DM) + 1e-6f);
    const float4* wr = reinterpret_cast<const float4*>(w);
    float4 wv = wr[tid];
    float4 o4;
    o4.x = v.x * r * wv.x;
    o4.y = v.y * r * wv.y;
    o4.z = v.z * r * wv.z;
    o4.w = v.w * r * wv.w;
    reinterpret_cast<float4*>(g_xn + (size_t)token * DM)[tid] = o4;
}

// ------------------------- SGEMM (NT: C[M,N] = A[M,K] * B[N,K]^T) -------------------------
// MODE 0: plain. MODE 1: dt epilogue (bias + softplus + softclamp). MODE 2: residual epilogue.
template <int MODE>
__global__ void __launch_bounds__(256) sgemm_nt(
    const float* __restrict__ Ag, const float* __restrict__ Bg, float* __restrict__ Cg,
    int M, int N, int K,
    const float* __restrict__ bias, const float* __restrict__ resid,
    const float* __restrict__ scale_ptr)
{
    __shared__ float As[16][128];
    __shared__ float Bs[16][128];
    const int tid = threadIdx.x;
    const int bm = blockIdx.y * 128;
    const int bn = blockIdx.x * 128;

    float acc[8][8];
#pragma unroll
    for (int i = 0; i < 8; i++)
#pragma unroll
        for (int j = 0; j < 8; j++) acc[i][j] = 0.f;

    const int tr = (tid >> 4) << 3;  // 0..120
    const int tc = (tid & 15) << 3;  // 0..120

    const float* Abase = Ag + (size_t)bm * K;
    const float* Bbase = Bg + (size_t)bn * K;

    for (int k0 = 0; k0 < K; k0 += 16) {
#pragma unroll
        for (int i = 0; i < 2; i++) {
            int e = tid * 2 + i;
            int row = e >> 2;
            int c4 = (e & 3) << 2;
            float4 av = *reinterpret_cast<const float4*>(Abase + (size_t)row * K + k0 + c4);
            As[c4 + 0][row] = av.x;
            As[c4 + 1][row] = av.y;
            As[c4 + 2][row] = av.z;
            As[c4 + 3][row] = av.w;
            float4 bv = *reinterpret_cast<const float4*>(Bbase + (size_t)row * K + k0 + c4);
            Bs[c4 + 0][row] = bv.x;
            Bs[c4 + 1][row] = bv.y;
            Bs[c4 + 2][row] = bv.z;
            Bs[c4 + 3][row] = bv.w;
        }
        __syncthreads();
#pragma unroll
        for (int k = 0; k < 16; k++) {
            float a[8], bb[8];
            *reinterpret_cast<float4*>(&a[0]) = *reinterpret_cast<const float4*>(&As[k][tr]);
            *reinterpret_cast<float4*>(&a[4]) = *reinterpret_cast<const float4*>(&As[k][tr + 4]);
            *reinterpret_cast<float4*>(&bb[0]) = *reinterpret_cast<const float4*>(&Bs[k][tc]);
            *reinterpret_cast<float4*>(&bb[4]) = *reinterpret_cast<const float4*>(&Bs[k][tc + 4]);
#pragma unroll
            for (int i = 0; i < 8; i++)
#pragma unroll
                for (int j = 0; j < 8; j++) acc[i][j] = fmaf(a[i], bb[j], acc[i][j]);
        }
        __syncthreads();
    }

    float scale = 0.f;
    if (MODE == 2) scale = 0.5f / (1.f + expf(-scale_ptr[0]));

#pragma unroll
    for (int i = 0; i < 8; i++) {
        size_t row = (size_t)(bm + tr + i);
#pragma unroll
        for (int j = 0; j < 8; j++) {
            int col = bn + tc + j;
            float v = acc[i][j];
            if (MODE == 1) {
                float pre = v + bias[col];
                // softplus (stable) then soft_clamp(.., 0.001, 0.1, 0.5)
                float sp = fmaxf(pre, 0.f) + log1pf(expf(-fabsf(pre)));
                float arg = (sp - 0.0505f) * (0.5f / (0.0495f + 1e-8f));
                v = tanhf(arg) * 0.099f + 0.0505f;
            } else if (MODE == 2) {
                v = resid[row * (size_t)N + col] + scale * v;
            }
            Cg[row * (size_t)N + col] = v;
        }
    }
}

// ------------------------- depthwise causal conv4 + SiLU -------------------------
__global__ void conv_silu_kernel(const float* __restrict__ conv_w, const float* __restrict__ conv_b)
{
    int token = blockIdx.x;
    int t = token & (LSEQ - 1);
    for (int d = threadIdx.x; d < DI; d += blockDim.x) {
        float4 w = *reinterpret_cast<const float4*>(conv_w + (size_t)d * 4);
        float acc = conv_b[d];
        const float* base = g_proj + (size_t)token * (2 * DI) + d;
        if (t >= 3) acc = fmaf(w.x, base[-3 * 2 * DI], acc);
        if (t >= 2) acc = fmaf(w.y, base[-2 * 2 * DI], acc);
        if (t >= 1) acc = fmaf(w.z, base[-1 * 2 * DI], acc);
        acc = fmaf(w.w, base[0], acc);
        float s = 1.f / (1.f + expf(-acc));
        g_xc[(size_t)token * DI + d] = acc * s;
    }
}

// ------------------------- Bp / Cp projections (N=16 each) -------------------------
// 4 tokens per block, 256 threads. Warp w handles outputs {w, w+8, w+16, w+24};
// outputs 0..15 -> W_B, 16..31 -> W_C.
__global__ void __launch_bounds__(256) bpcp_kernel(const float* __restrict__ W_B, const float* __restrict__ W_C)
{
    __shared__ float sx[4][DI];
    int tok0 = blockIdx.x * 4;
    int tid = threadIdx.x;
    for (int i = tid; i < 4 * DI; i += 256) {
        int r = i >> 11;
        int dd = i & (DI - 1);
        sx[r][dd] = g_xc[(size_t)(tok0 + r) * DI + dd];
    }
    __syncthreads();
    int wid = tid >> 5, lane = tid & 31;
#pragma unroll
    for (int oo = 0; oo < 4; oo++) {
        int o = wid + oo * 8;
        const float* Wr = (o < 16) ? (W_B + (size_t)o * DI) : (W_C + (size_t)(o - 16) * DI);
        float a0 = 0.f, a1 = 0.f, a2 = 0.f, a3 = 0.f;
        for (int dd = lane; dd < DI; dd += 32) {
            float w = Wr[dd];
            a0 = fmaf(w, sx[0][dd], a0);
            a1 = fmaf(w, sx[1][dd], a1);
            a2 = fmaf(w, sx[2][dd], a2);
            a3 = fmaf(w, sx[3][dd], a3);
        }
#pragma unroll
        for (int off = 16; off; off >>= 1) {
            a0 += __shfl_xor_sync(0xffffffffu, a0, off);
            a1 += __shfl_xor_sync(0xffffffffu, a1, off);
            a2 += __shfl_xor_sync(0xffffffffu, a2, off);
            a3 += __shfl_xor_sync(0xffffffffu, a3, off);
        }
        if (lane == 0) {
            float* outp = (o < 16) ? g_Bp : g_Cp;
            int oc = (o < 16) ? o : (o - 16);
            outp[(tok0 + 0) * DS + oc] = a0;
            outp[(tok0 + 1) * DS + oc] = a1;
            outp[(tok0 + 2) * DS + oc] = a2;
            outp[(tok0 + 3) * DS + oc] = a3;
        }
    }
}

// ------------------------- selective scan (cluster of 8 CTAs per batch) -------------------------
template <int NS>
__device__ __forceinline__ void scan_chunk(
    int t0, int cidx, int tid,
    float* h, const float* A, float Dv,
    const float* dtb, const float* xcb, float* yb,
    const float* Bpb, const float* Cpb,
    float (*sB)[16], float (*sC)[16],
    float* warp_part, float* slot, float* s_fac, uint32_t slot_u32)
{
    __syncthreads();  // protect smem reuse across chunks
    for (int i = tid; i < NS * 16; i += 256) {
        int s = i >> 4, n = i & 15;
        sB[s][n] = Bpb[(size_t)(t0 + s) * DS + n];
        sC[s][n] = Cpb[(size_t)(t0 + s) * DS + n];
    }
    float dtv[NS], xcv[NS];
#pragma unroll
    for (int s = 0; s < NS; s++) {
        dtv[s] = dtb[(size_t)(t0 + s) * DI];
        xcv[s] = xcb[(size_t)(t0 + s) * DI];
    }
    __syncthreads();

#pragma unroll
    for (int s = 0; s < NS; s++) {
        float dt_ = dtv[s], xc_ = xcv[s];
        float dtx = dt_ * xc_;
#pragma unroll
        for (int n = 0; n < 16; n++) {
            float z = dt_ * A[n];
            // e = 16*tanh(z/16); polynomial exact for |z| < 1 (fallback for safety)
            float z2 = z * z;
            float e = z + z * z2 * fmaf(z2, 2.0345052e-6f, -1.3020833e-3f);
            if (fabsf(z) >= 1.0f) e = 16.f * tanhf(z * 0.0625f);
            float dA = __expf(e);
            h[n] = fmaf(h[n], dA, dtx * sB[s][n]);
        }
        if (s == 0) {  // t0 % 10 == 0 always: global norm event
            float ss = 0.f;
#pragma unroll
            for (int n = 0; n < 16; n++) ss = fmaf(h[n], h[n], ss);
#pragma unroll
            for (int o = 16; o; o >>= 1) ss += __shfl_xor_sync(0xffffffffu, ss, o);
            if ((tid & 31) == 0) warp_part[tid >> 5] = ss;
            __syncthreads();
            int par = cidx & 1;
            if (tid == 0) {
                float blk = 0.f;
#pragma unroll
                for (int w = 0; w < 8; w++) blk += warp_part[w];
                slot[par] = blk;
            }
            asm volatile("barrier.cluster.arrive.aligned;" ::: "memory");
            asm volatile("barrier.cluster.wait.aligned;" ::: "memory");
            if (tid == 0) {
                float tot = 0.f;
#pragma unroll
                for (int r = 0; r < 8; r++) {
                    uint32_t rem;
                    asm volatile("mapa.shared::cluster.u32 %0, %1, %2;"
                                 : "=r"(rem)
                                 : "r"(slot_u32 + (uint32_t)(par * 4)), "r"(r));
                    float v;
                    asm volatile("ld.shared::cluster.f32 %0, [%1];" : "=f"(v) : "r"(rem));
                    tot += v;
                }
                float nrm = sqrtf(tot);
                *s_fac = fminf(20.f / (nrm + 1e-8f), 1.f);
            }
            __syncthreads();
            float fac = *s_fac;
#pragma unroll
            for (int n = 0; n < 16; n++) h[n] *= fac;
        }
        float y = Dv * xc_;
#pragma unroll
        for (int n = 0; n < 16; n++) y = fmaf(h[n], sC[s][n], y);
        yb[(size_t)(t0 + s) * DI] = y;
    }
}

__global__ void __cluster_dims__(8, 1, 1) __launch_bounds__(256)
scan_kernel(const float* __restrict__ A_log, const float* __restrict__ Dp)
{
    __shared__ float sB[10][16], sC[10][16];
    __shared__ float warp_part[8];
    __shared__ float slot[2];
    __shared__ float s_fac;

    int tid = threadIdx.x;
    int b = blockIdx.x >> 3;
    int rk = blockIdx.x & 7;
    int d = rk * 256 + tid;

    float A[16], h[16];
#pragma unroll
    for (int n = 0; n < 16; n++) {
        float al = A_log[(size_t)d * 16 + n];
        A[n] = -expf(10.f * tanhf(0.1f * al));  // -exp(soft_clamp(A_log,-5,5,0.5))
        h[n] = 0.f;
    }
    float Dv = Dp[d];

    const float* dtb = g_dt + (size_t)b * LSEQ * DI + d;
    const float* xcb = g_xc + (size_t)b * LSEQ * DI + d;
    float* yb = g_xssm + (size_t)b * LSEQ * DI + d;
    const float* Bpb = g_Bp + (size_t)b * LSEQ * DS;
    const float* Cpb = g_Cp + (size_t)b * LSEQ * DS;

    uint32_t slot_u32 = (uint32_t)__cvta_generic_to_shared(slot);

    for (int c = 0; c < 102; c++)
        scan_chunk<10>(c * 10, c, tid, h, A, Dv, dtb, xcb, yb, Bpb, Cpb,
                       sB, sC, warp_part, slot, &s_fac, slot_u32);
    scan_chunk<4>(1020, 102, tid, h, A, Dv, dtb, xcb, yb, Bpb, Cpb,
                  sB, sC, warp_part, slot, &s_fac, slot_u32);
}

// ------------------------- gate (x_ssm * silu(gate)) -------------------------
__global__ void gate_kernel()
{
    size_t i = (size_t)blockIdx.x * blockDim.x + threadIdx.x;
    int token = (int)(i >> 11);
    int dd = (int)(i & (DI - 1));
    float g = g_proj[(size_t)token * (2 * DI) + DI + dd];
    float sg = g / (1.f + expf(-g));
    g_gated[i] = g_xssm[i] * sg;
}

// ------------------------- launch -------------------------
extern "C" void kernel_launch(void* const* d_in, const int* in_sizes, int n_in,
                              void* d_out, int out_size)
{
    const float* x       = (const float*)d_in[0];
    const float* norm_w  = (const float*)d_in[1];
    const float* W_in    = (const float*)d_in[2];
    const float* conv_w  = (const float*)d_in[3];
    const float* conv_b  = (const float*)d_in[4];
    const float* W_dt    = (const float*)d_in[5];
    const float* b_dt    = (const float*)d_in[6];
    const float* W_B     = (const float*)d_in[7];
    const float* W_C     = (const float*)d_in[8];
    const float* A_log   = (const float*)d_in[9];
    const float* D_param = (const float*)d_in[10];
    const float* W_out   = (const float*)d_in[11];
    const float* r_scale = (const float*)d_in[12];
    float* out = (float*)d_out;

    void *p_xn, *p_proj, *p_xc, *p_dt, *p_gated;
    cudaGetSymbolAddress(&p_xn, g_xn);
    cudaGetSymbolAddress(&p_proj, g_proj);
    cudaGetSymbolAddress(&p_xc, g_xc);
    cudaGetSymbolAddress(&p_dt, g_dt);
    cudaGetSymbolAddress(&p_gated, g_gated);

    // 1. RMSNorm
    rmsnorm_kernel<<<NTOK, 256>>>(x, norm_w);
    // 2. in-projection: proj[2048,4096] = xn[2048,1024] @ W_in^T
    sgemm_nt<0><<<dim3(4096 / 128, NTOK / 128), 256>>>(
        (const float*)p_xn, W_in, (float*)p_proj, NTOK, 4096, 1024, nullptr, nullptr, nullptr);
    // 3. depthwise conv + silu
    conv_silu_kernel<<<NTOK, 256>>>(conv_w, conv_b);
    // 4. dt = softclamp(softplus(xc @ W_dt^T + b_dt))
    sgemm_nt<1><<<dim3(DI / 128, NTOK / 128), 256>>>(
        (const float*)p_xc, W_dt, (float*)p_dt, NTOK, DI, DI, b_dt, nullptr, nullptr);
    // 5. Bp / Cp
    bpcp_kernel<<<NTOK / 4, 256>>>(W_B, W_C);
    // 6. selective scan (2 clusters of 8 CTAs)
    scan_kernel<<<16, 256>>>(A_log, D_param);
    // 7. gating
    gate_kernel<<<(NTOK * DI) / 256, 256>>>();
    // 8. out-projection + residual
    sgemm_nt<2><<<dim3(DM / 128, NTOK / 128), 256>>>(
        (const float*)p_gated, W_out, out, NTOK, DM, DI, nullptr, x, r_scale);
}